// round 9
// baseline (speedup 1.0000x reference)
#include <cuda_runtime.h>
#include <cuda_bf16.h>

#define D_FEAT 128
#define D4 (D_FEAT / 4)      // 32 float4 per row
#define EPS 1e-6f

// ============ fast path: nodes_per_graph == 512, pipelined persistent =======
// Tile = (graph, 4 float4 columns = 16 features). 8 tiles per graph.
// 256 threads: c = t&3 (column), rg = t>>2 (row group 0..63), 8 rows/thread.
// Double-buffered register tiles; next tile's loads issued before current
// tile's reduce+store so the read stream never drains.
#define PT_THREADS 256
#define PT_CHUNK4  4
#define PT_ITERS   8
#define PT_NWARPS  (PT_THREADS / 32)   // 8

__device__ __forceinline__ void gn_load(const float4* __restrict__ x, int tile,
                                        int c, int rg, float4 (&v)[PT_ITERS])
{
    const int g     = tile >> 3;
    const int chunk = tile & 7;
    const float4* xg = x + (size_t)g * 512 * D4 + chunk * PT_CHUNK4 + c;
    #pragma unroll
    for (int i = 0; i < PT_ITERS; i++)
        v[i] = __ldcs(&xg[(size_t)(rg + i * 64) * D4]);
}

__device__ __forceinline__ void gn_process(
    float4 (&v)[PT_ITERS], int tile, int c, int rg, int t,
    const int*    __restrict__ n_node,
    const float4* __restrict__ mean_scale,
    const float4* __restrict__ scale,
    const float4* __restrict__ bias,
    float4* __restrict__ out,
    float4 (*sh_s)[PT_CHUNK4], float4 (*sh_s2)[PT_CHUNK4])
{
    const int g     = tile >> 3;
    const int chunk = tile & 7;
    const int col4  = chunk * PT_CHUNK4 + c;
    const int lane  = t & 31;
    const int w     = t >> 5;

    // ---- accumulate ----
    float4 s  = make_float4(0.f, 0.f, 0.f, 0.f);
    float4 s2 = make_float4(0.f, 0.f, 0.f, 0.f);
    #pragma unroll
    for (int i = 0; i < PT_ITERS; i++) {
        s.x += v[i].x; s.y += v[i].y; s.z += v[i].z; s.w += v[i].w;
        s2.x = fmaf(v[i].x, v[i].x, s2.x);
        s2.y = fmaf(v[i].y, v[i].y, s2.y);
        s2.z = fmaf(v[i].z, v[i].z, s2.z);
        s2.w = fmaf(v[i].w, v[i].w, s2.w);
    }

    // ---- intra-warp: threads sharing a column are lanes c, c+4, ..., c+28 ----
    #pragma unroll
    for (int m = 4; m <= 16; m <<= 1) {
        s.x  += __shfl_xor_sync(0xffffffffu, s.x,  m);
        s.y  += __shfl_xor_sync(0xffffffffu, s.y,  m);
        s.z  += __shfl_xor_sync(0xffffffffu, s.z,  m);
        s.w  += __shfl_xor_sync(0xffffffffu, s.w,  m);
        s2.x += __shfl_xor_sync(0xffffffffu, s2.x, m);
        s2.y += __shfl_xor_sync(0xffffffffu, s2.y, m);
        s2.z += __shfl_xor_sync(0xffffffffu, s2.z, m);
        s2.w += __shfl_xor_sync(0xffffffffu, s2.w, m);
    }

    // ---- cross-warp: publish 8x4 partial pairs, 1 LDS pair per thread ----
    if (lane < PT_CHUNK4) {
        sh_s [w][lane] = s;
        sh_s2[w][lane] = s2;
    }
    __syncthreads();
    float4 a  = sh_s [lane >> 2][lane & 3];   // pair (warp k = lane>>2, col = lane&3)
    float4 b2 = sh_s2[lane >> 2][lane & 3];
    __syncthreads();                           // smem reusable next call

    // reduce across k (lane bits 2..4); every lane ends with total for col = lane&3 = c
    #pragma unroll
    for (int m = 4; m <= 16; m <<= 1) {
        a.x  += __shfl_xor_sync(0xffffffffu, a.x,  m);
        a.y  += __shfl_xor_sync(0xffffffffu, a.y,  m);
        a.z  += __shfl_xor_sync(0xffffffffu, a.z,  m);
        a.w  += __shfl_xor_sync(0xffffffffu, a.w,  m);
        b2.x += __shfl_xor_sync(0xffffffffu, b2.x, m);
        b2.y += __shfl_xor_sync(0xffffffffu, b2.y, m);
        b2.z += __shfl_xor_sync(0xffffffffu, b2.z, m);
        b2.w += __shfl_xor_sync(0xffffffffu, b2.w, m);
    }

    // ---- per-feature constants (L1-hot after first tile) ----
    const float inv_n = 1.0f / (float)__ldg(&n_node[g]);
    const float4 ms = __ldg(&mean_scale[col4]);
    const float4 sc = __ldg(&scale[col4]);
    const float4 bi = __ldg(&bias[col4]);

    float4 mul, add;
    {
        float mean, m, var;
        mean = a.x * inv_n; m = mean * ms.x;
        var  = b2.x * inv_n - 2.0f * m * mean + m * m;
        mul.x = rsqrtf(var + EPS) * sc.x; add.x = bi.x - m * mul.x;

        mean = a.y * inv_n; m = mean * ms.y;
        var  = b2.y * inv_n - 2.0f * m * mean + m * m;
        mul.y = rsqrtf(var + EPS) * sc.y; add.y = bi.y - m * mul.y;

        mean = a.z * inv_n; m = mean * ms.z;
        var  = b2.z * inv_n - 2.0f * m * mean + m * m;
        mul.z = rsqrtf(var + EPS) * sc.z; add.z = bi.z - m * mul.z;

        mean = a.w * inv_n; m = mean * ms.w;
        var  = b2.w * inv_n - 2.0f * m * mean + m * m;
        mul.w = rsqrtf(var + EPS) * sc.w; add.w = bi.w - m * mul.w;
    }

    // ---- write y from registers ----
    float4* og = out + (size_t)g * 512 * D4 + chunk * PT_CHUNK4 + c;
    #pragma unroll
    for (int i = 0; i < PT_ITERS; i++) {
        float4 y;
        y.x = fmaf(v[i].x, mul.x, add.x);
        y.y = fmaf(v[i].y, mul.y, add.y);
        y.z = fmaf(v[i].z, mul.z, add.z);
        y.w = fmaf(v[i].w, mul.w, add.w);
        og[(size_t)(rg + i * 64) * D4] = y;
    }
}

__global__ __launch_bounds__(PT_THREADS, 2)
void graphnorm_pipe(const float4* __restrict__ x,
                    const int*    __restrict__ n_node,
                    const float4* __restrict__ mean_scale,
                    const float4* __restrict__ scale,
                    const float4* __restrict__ bias,
                    float4* __restrict__ out,
                    int ntiles)
{
    __shared__ float4 sh_s [PT_NWARPS][PT_CHUNK4];
    __shared__ float4 sh_s2[PT_NWARPS][PT_CHUNK4];

    const int t  = threadIdx.x;
    const int c  = t & (PT_CHUNK4 - 1);
    const int rg = t >> 2;
    const int stride = gridDim.x;

    int tile = blockIdx.x;
    if (tile >= ntiles) return;

    float4 vA[PT_ITERS], vB[PT_ITERS];
    gn_load(x, tile, c, rg, vA);

    bool useA = true;
    for (;;) {
        const int nxt = tile + stride;
        if (useA) {
            if (nxt < ntiles) gn_load(x, nxt, c, rg, vB);
            gn_process(vA, tile, c, rg, t, n_node, mean_scale, scale, bias, out,
                       sh_s, sh_s2);
        } else {
            if (nxt < ntiles) gn_load(x, nxt, c, rg, vA);
            gn_process(vB, tile, c, rg, t, n_node, mean_scale, scale, bias, out,
                       sh_s, sh_s2);
        }
        if (nxt >= ntiles) break;
        tile = nxt;
        useA = !useA;
    }
}

// ---------------- generic fallback (two-pass, any nodes_per_graph) ----------
#define GTHREADS 512
#define GROWGROUPS (GTHREADS / D4)

__global__ __launch_bounds__(GTHREADS, 2)
void graphnorm_generic(const float4* __restrict__ x,
                       const int*    __restrict__ n_node,
                       const float4* __restrict__ mean_scale,
                       const float4* __restrict__ scale,
                       const float4* __restrict__ bias,
                       float4* __restrict__ out,
                       int nodes_per_graph)
{
    const int g     = blockIdx.x;
    const int t     = threadIdx.x;
    const int lane4 = t & (D4 - 1);
    const int rg    = t >> 5;

    const float4* xg = x   + (size_t)g * nodes_per_graph * D4;
    float4*       og = out + (size_t)g * nodes_per_graph * D4;

    float4 s  = make_float4(0.f, 0.f, 0.f, 0.f);
    float4 s2 = make_float4(0.f, 0.f, 0.f, 0.f);
    for (int r = rg; r < nodes_per_graph; r += GROWGROUPS) {
        float4 v = xg[(size_t)r * D4 + lane4];
        s.x += v.x; s.y += v.y; s.z += v.z; s.w += v.w;
        s2.x = fmaf(v.x, v.x, s2.x);
        s2.y = fmaf(v.y, v.y, s2.y);
        s2.z = fmaf(v.z, v.z, s2.z);
        s2.w = fmaf(v.w, v.w, s2.w);
    }

    __shared__ float4 sh_s [GROWGROUPS][D4];
    __shared__ float4 sh_s2[GROWGROUPS][D4];
    sh_s [rg][lane4] = s;
    sh_s2[rg][lane4] = s2;
    __syncthreads();

    #pragma unroll
    for (int step = GROWGROUPS / 2; step >= 1; step >>= 1) {
        if (rg < step) {
            float4 a = sh_s[rg][lane4],  b = sh_s[rg + step][lane4];
            a.x += b.x; a.y += b.y; a.z += b.z; a.w += b.w;
            sh_s[rg][lane4] = a;
            float4 cc = sh_s2[rg][lane4], d = sh_s2[rg + step][lane4];
            cc.x += d.x; cc.y += d.y; cc.z += d.z; cc.w += d.w;
            sh_s2[rg][lane4] = cc;
        }
        __syncthreads();
    }

    const float inv_n = 1.0f / (float)n_node[g];
    float4 tot  = sh_s [0][lane4];
    float4 tot2 = sh_s2[0][lane4];
    float4 ms = __ldg(&mean_scale[lane4]);
    float4 sc = __ldg(&scale[lane4]);
    float4 bi = __ldg(&bias[lane4]);

    float4 mul, add;
    {
        float mean, m, var;
        mean = tot.x * inv_n; m = mean * ms.x;
        var  = tot2.x * inv_n - 2.0f * m * mean + m * m;
        mul.x = rsqrtf(var + EPS) * sc.x; add.x = bi.x - m * mul.x;

        mean = tot.y * inv_n; m = mean * ms.y;
        var  = tot2.y * inv_n - 2.0f * m * mean + m * m;
        mul.y = rsqrtf(var + EPS) * sc.y; add.y = bi.y - m * mul.y;

        mean = tot.z * inv_n; m = mean * ms.z;
        var  = tot2.z * inv_n - 2.0f * m * mean + m * m;
        mul.z = rsqrtf(var + EPS) * sc.z; add.z = bi.z - m * mul.z;

        mean = tot.w * inv_n; m = mean * ms.w;
        var  = tot2.w * inv_n - 2.0f * m * mean + m * m;
        mul.w = rsqrtf(var + EPS) * sc.w; add.w = bi.w - m * mul.w;
    }

    for (int r = rg; r < nodes_per_graph; r += GROWGROUPS) {
        float4 v = xg[(size_t)r * D4 + lane4];
        float4 y;
        y.x = fmaf(v.x, mul.x, add.x);
        y.y = fmaf(v.y, mul.y, add.y);
        y.z = fmaf(v.z, mul.z, add.z);
        y.w = fmaf(v.w, mul.w, add.w);
        og[(size_t)r * D4 + lane4] = y;
    }
}

extern "C" void kernel_launch(void* const* d_in, const int* in_sizes, int n_in,
                              void* d_out, int out_size)
{
    const float* x          = (const float*)d_in[0];
    const int*   n_node     = (const int*)d_in[1];
    const float* mean_scale = (const float*)d_in[2];
    const float* scale      = (const float*)d_in[3];
    const float* bias       = (const float*)d_in[4];
    float*       out        = (float*)d_out;

    const int n_graph = in_sizes[1];
    const int total_nodes = in_sizes[0] / D_FEAT;
    const int nodes_per_graph = total_nodes / n_graph;

    if (nodes_per_graph == 512) {
        int dev = 0, sms = 148;
        cudaGetDevice(&dev);
        cudaDeviceGetAttribute(&sms, cudaDevAttrMultiProcessorCount, dev);
        const int ntiles = n_graph * 8;       // 8 tiles (16 features each) per graph
        int grid = 2 * sms;
        if (grid > ntiles) grid = ntiles;
        graphnorm_pipe<<<grid, PT_THREADS>>>(
            (const float4*)x, n_node,
            (const float4*)mean_scale, (const float4*)scale, (const float4*)bias,
            (float4*)out, ntiles);
    } else {
        graphnorm_generic<<<n_graph, GTHREADS>>>(
            (const float4*)x, n_node,
            (const float4*)mean_scale, (const float4*)scale, (const float4*)bias,
            (float4*)out, nodes_per_graph);
    }
}

// round 12
// speedup vs baseline: 1.2279x; 1.2279x over previous
#include <cuda_runtime.h>
#include <cuda_bf16.h>

#define D_FEAT 128
#define D4 (D_FEAT / 4)      // 32 float4 per row
#define EPS 1e-6f

// ---------------- fast path: nodes_per_graph == 512 -------------------------
// One CTA = one (graph, 32-feature chunk). 512 threads (2 CTAs/SM = 32 warps),
// each thread caches 8 float4; single DRAM read + single DRAM write.
// Epilogue is all-parallel and LDS-light: shfl -> 4KB smem -> shfl.
#define CHUNK4   8           // float4 columns per chunk (32 features = 128B row)
#define FTHREADS 512
#define RG_FAST  (FTHREADS / CHUNK4)   // 64 row groups
#define ITERS    8                     // 512 / 64
#define NWARPS   (FTHREADS / 32)       // 16

__global__ __launch_bounds__(FTHREADS, 2)
void graphnorm_fast(const float4* __restrict__ x,
                    const int*    __restrict__ n_node,
                    const float4* __restrict__ mean_scale,
                    const float4* __restrict__ scale,
                    const float4* __restrict__ bias,
                    float4* __restrict__ out)
{
    const int b     = blockIdx.x;
    const int g     = b >> 2;           // graph
    const int chunk = b & 3;            // which 32-feature chunk
    const int t     = threadIdx.x;
    const int c     = t & (CHUNK4 - 1); // column within chunk (0..7)
    const int rg    = t >> 3;           // row group (0..63)
    const int lane  = t & 31;
    const int w     = t >> 5;
    const int col4  = chunk * CHUNK4 + c;   // global float4 column

    const size_t base = (size_t)g * 512 * D4 + col4;
    const float4* xg = x   + base;
    float4*       og = out + base;

    // ---- load 8 rows into registers, accumulate sum / sumsq ----
    float4 v[ITERS];
    float4 s  = make_float4(0.f, 0.f, 0.f, 0.f);
    float4 s2 = make_float4(0.f, 0.f, 0.f, 0.f);
    #pragma unroll
    for (int i = 0; i < ITERS; i++) {
        v[i] = xg[(size_t)(rg + i * RG_FAST) * D4];
    }
    #pragma unroll
    for (int i = 0; i < ITERS; i++) {
        s.x += v[i].x; s.y += v[i].y; s.z += v[i].z; s.w += v[i].w;
        s2.x = fmaf(v[i].x, v[i].x, s2.x);
        s2.y = fmaf(v[i].y, v[i].y, s2.y);
        s2.z = fmaf(v[i].z, v[i].z, s2.z);
        s2.w = fmaf(v[i].w, v[i].w, s2.w);
    }

    // ---- intra-warp reduce: threads sharing a column are lanes c, c+8, c+16, c+24
    #pragma unroll
    for (int m = 8; m <= 16; m <<= 1) {
        s.x  += __shfl_xor_sync(0xffffffffu, s.x,  m);
        s.y  += __shfl_xor_sync(0xffffffffu, s.y,  m);
        s.z  += __shfl_xor_sync(0xffffffffu, s.z,  m);
        s.w  += __shfl_xor_sync(0xffffffffu, s.w,  m);
        s2.x += __shfl_xor_sync(0xffffffffu, s2.x, m);
        s2.y += __shfl_xor_sync(0xffffffffu, s2.y, m);
        s2.z += __shfl_xor_sync(0xffffffffu, s2.z, m);
        s2.w += __shfl_xor_sync(0xffffffffu, s2.w, m);
    }

    // ---- publish 16 warp-partials (lanes 0..7 hold them) ----
    __shared__ float4 sh_s [NWARPS][CHUNK4];
    __shared__ float4 sh_s2[NWARPS][CHUNK4];
    if (lane < CHUNK4) {
        sh_s [w][lane] = s;
        sh_s2[w][lane] = s2;
    }
    __syncthreads();

    // ---- stage 2 (all threads, conflict-free, 4 pairs each):
    // lane reads slots k = (lane>>3) + {0,4,8,12}, col = lane&7, sums them,
    // then shfl over lane bits 3..4 combines the 4 k-groups.
    const int k0 = lane >> 3;           // 0..3
    const int cc = lane & 7;            // == c
    float4 a  = sh_s [k0     ][cc];
    float4 b2 = sh_s2[k0     ][cc];
    #pragma unroll
    for (int j = 1; j < 4; j++) {
        float4 p = sh_s [k0 + 4*j][cc];
        float4 q = sh_s2[k0 + 4*j][cc];
        a.x  += p.x;  a.y  += p.y;  a.z  += p.z;  a.w  += p.w;
        b2.x += q.x;  b2.y += q.y;  b2.z += q.z;  b2.w += q.w;
    }
    #pragma unroll
    for (int m = 8; m <= 16; m <<= 1) {
        a.x  += __shfl_xor_sync(0xffffffffu, a.x,  m);
        a.y  += __shfl_xor_sync(0xffffffffu, a.y,  m);
        a.z  += __shfl_xor_sync(0xffffffffu, a.z,  m);
        a.w  += __shfl_xor_sync(0xffffffffu, a.w,  m);
        b2.x += __shfl_xor_sync(0xffffffffu, b2.x, m);
        b2.y += __shfl_xor_sync(0xffffffffu, b2.y, m);
        b2.z += __shfl_xor_sync(0xffffffffu, b2.z, m);
        b2.w += __shfl_xor_sync(0xffffffffu, b2.w, m);
    }

    // ---- per-feature constants (parallel across all threads; L2-hot) ----
    const float inv_n = 1.0f / (float)__ldg(&n_node[g]);
    const float4 ms = __ldg(&mean_scale[col4]);
    const float4 sc = __ldg(&scale[col4]);
    const float4 bi = __ldg(&bias[col4]);

    float4 mul, add;
    {
        float mean, m, var;
        mean = a.x * inv_n; m = mean * ms.x;
        var  = b2.x * inv_n - 2.0f * m * mean + m * m;
        mul.x = rsqrtf(var + EPS) * sc.x; add.x = bi.x - m * mul.x;

        mean = a.y * inv_n; m = mean * ms.y;
        var  = b2.y * inv_n - 2.0f * m * mean + m * m;
        mul.y = rsqrtf(var + EPS) * sc.y; add.y = bi.y - m * mul.y;

        mean = a.z * inv_n; m = mean * ms.z;
        var  = b2.z * inv_n - 2.0f * m * mean + m * m;
        mul.z = rsqrtf(var + EPS) * sc.z; add.z = bi.z - m * mul.z;

        mean = a.w * inv_n; m = mean * ms.w;
        var  = b2.w * inv_n - 2.0f * m * mean + m * m;
        mul.w = rsqrtf(var + EPS) * sc.w; add.w = bi.w - m * mul.w;
    }

    // ---- write y straight from registers ----
    #pragma unroll
    for (int i = 0; i < ITERS; i++) {
        float4 y;
        y.x = fmaf(v[i].x, mul.x, add.x);
        y.y = fmaf(v[i].y, mul.y, add.y);
        y.z = fmaf(v[i].z, mul.z, add.z);
        y.w = fmaf(v[i].w, mul.w, add.w);
        og[(size_t)(rg + i * RG_FAST) * D4] = y;
    }
}

// ---------------- generic fallback (two-pass, any nodes_per_graph) ----------
#define GTHREADS 512
#define GROWGROUPS (GTHREADS / D4)

__global__ __launch_bounds__(GTHREADS, 2)
void graphnorm_generic(const float4* __restrict__ x,
                       const int*    __restrict__ n_node,
                       const float4* __restrict__ mean_scale,
                       const float4* __restrict__ scale,
                       const float4* __restrict__ bias,
                       float4* __restrict__ out,
                       int nodes_per_graph)
{
    const int g     = blockIdx.x;
    const int t     = threadIdx.x;
    const int lane4 = t & (D4 - 1);
    const int rg    = t >> 5;

    const float4* xg = x   + (size_t)g * nodes_per_graph * D4;
    float4*       og = out + (size_t)g * nodes_per_graph * D4;

    float4 s  = make_float4(0.f, 0.f, 0.f, 0.f);
    float4 s2 = make_float4(0.f, 0.f, 0.f, 0.f);
    for (int r = rg; r < nodes_per_graph; r += GROWGROUPS) {
        float4 v = xg[(size_t)r * D4 + lane4];
        s.x += v.x; s.y += v.y; s.z += v.z; s.w += v.w;
        s2.x = fmaf(v.x, v.x, s2.x);
        s2.y = fmaf(v.y, v.y, s2.y);
        s2.z = fmaf(v.z, v.z, s2.z);
        s2.w = fmaf(v.w, v.w, s2.w);
    }

    __shared__ float4 sh_s [GROWGROUPS][D4];
    __shared__ float4 sh_s2[GROWGROUPS][D4];
    sh_s [rg][lane4] = s;
    sh_s2[rg][lane4] = s2;
    __syncthreads();

    #pragma unroll
    for (int step = GROWGROUPS / 2; step >= 1; step >>= 1) {
        if (rg < step) {
            float4 a = sh_s[rg][lane4],  b = sh_s[rg + step][lane4];
            a.x += b.x; a.y += b.y; a.z += b.z; a.w += b.w;
            sh_s[rg][lane4] = a;
            float4 cc = sh_s2[rg][lane4], d = sh_s2[rg + step][lane4];
            cc.x += d.x; cc.y += d.y; cc.z += d.z; cc.w += d.w;
            sh_s2[rg][lane4] = cc;
        }
        __syncthreads();
    }

    const float inv_n = 1.0f / (float)n_node[g];
    float4 tot  = sh_s [0][lane4];
    float4 tot2 = sh_s2[0][lane4];
    float4 ms = __ldg(&mean_scale[lane4]);
    float4 sc = __ldg(&scale[lane4]);
    float4 bi = __ldg(&bias[lane4]);

    float4 mul, add;
    {
        float mean, m, var;
        mean = tot.x * inv_n; m = mean * ms.x;
        var  = tot2.x * inv_n - 2.0f * m * mean + m * m;
        mul.x = rsqrtf(var + EPS) * sc.x; add.x = bi.x - m * mul.x;

        mean = tot.y * inv_n; m = mean * ms.y;
        var  = tot2.y * inv_n - 2.0f * m * mean + m * m;
        mul.y = rsqrtf(var + EPS) * sc.y; add.y = bi.y - m * mul.y;

        mean = tot.z * inv_n; m = mean * ms.z;
        var  = tot2.z * inv_n - 2.0f * m * mean + m * m;
        mul.z = rsqrtf(var + EPS) * sc.z; add.z = bi.z - m * mul.z;

        mean = tot.w * inv_n; m = mean * ms.w;
        var  = tot2.w * inv_n - 2.0f * m * mean + m * m;
        mul.w = rsqrtf(var + EPS) * sc.w; add.w = bi.w - m * mul.w;
    }

    for (int r = rg; r < nodes_per_graph; r += GROWGROUPS) {
        float4 v = xg[(size_t)r * D4 + lane4];
        float4 y;
        y.x = fmaf(v.x, mul.x, add.x);
        y.y = fmaf(v.y, mul.y, add.y);
        y.z = fmaf(v.z, mul.z, add.z);
        y.w = fmaf(v.w, mul.w, add.w);
        og[(size_t)r * D4 + lane4] = y;
    }
}

extern "C" void kernel_launch(void* const* d_in, const int* in_sizes, int n_in,
                              void* d_out, int out_size)
{
    const float* x          = (const float*)d_in[0];
    const int*   n_node     = (const int*)d_in[1];
    const float* mean_scale = (const float*)d_in[2];
    const float* scale      = (const float*)d_in[3];
    const float* bias       = (const float*)d_in[4];
    float*       out        = (float*)d_out;

    const int n_graph = in_sizes[1];
    const int total_nodes = in_sizes[0] / D_FEAT;
    const int nodes_per_graph = total_nodes / n_graph;

    if (nodes_per_graph == 512) {
        graphnorm_fast<<<n_graph * 4, FTHREADS>>>(
            (const float4*)x, n_node,
            (const float4*)mean_scale, (const float4*)scale, (const float4*)bias,
            (float4*)out);
    } else {
        graphnorm_generic<<<n_graph, GTHREADS>>>(
            (const float4*)x, n_node,
            (const float4*)mean_scale, (const float4*)scale, (const float4*)bias,
            (float4*)out, nodes_per_graph);
    }
}